// round 15
// baseline (speedup 1.0000x reference)
#include <cuda_runtime.h>
#include <cuda_bf16.h>
#include <cstdint>

#define N1MAX 15000
#define N2MAX 60000

// ---------------- device scratch (static, no allocs) -------------------------
__device__ float g_x   [N2MAX * 128];                 // concat(x1 raw, feats2)
__device__ float g_pre [N2MAX * 64];                  // conv1 pre-BN
__device__ float g_msg [27u * N2MAX * 64];            // per-entry MMA outputs
__device__ int   g_ent  [27 * N2MAX];                 // per-tap compacted src
__device__ int   g_entup[ 8 * N2MAX];
__device__ int   g_pos  [27 * N2MAX];                 // (tap,i) -> slot or -1
__device__ int   g_posup[N2MAX];
__device__ int   g_cnt  [27];                         // zeroed by build_tiles
__device__ int   g_cntup[8];                          // (post-consumption)
// weight images: [t][part(hi,lo)][o(64)][k(CI)] bf16, k contiguous
__device__ unsigned short g_Bup[8  * 2 * 64 * 128];
__device__ unsigned short g_B1 [27 * 2 * 64 * 128];
__device__ unsigned short g_B2 [27 * 2 * 64 * 64];
__device__ float g_part[1024 * 64 * 2];               // BN partials (64-row blocks)
__device__ float g_bn  [128];                          // scale[64], shift[64]
// exact tile lists (parallel-built)
__device__ int g_tileT [13000];
__device__ int g_tileB [13000];
__device__ int g_tileN [13000];
__device__ int g_tileTu[4096];
__device__ int g_tileBu[4096];
__device__ int g_tileNu[4096];
__device__ int g_ntiles;
__device__ int g_ntilesu;

// ---------------- weight split (template CI -> shift divisions) --------------
template <int CI>
__device__ __forceinline__ void wsplit_one(const float* __restrict__ w,
                                           unsigned short* __restrict__ dst,
                                           int j) {
    constexpr int PER = CI * 64;
    int t = j / PER;
    int r = j & (PER - 1);
    int k = r >> 6;
    int o = r & 63;
    float v = w[j];
    __nv_bfloat16 h = __float2bfloat16(v);
    __nv_bfloat16 l = __float2bfloat16(v - __bfloat162float(h));
    unsigned short* base = dst + (size_t)t * (2 * 64 * CI);
    base[o * CI + k]           = *(unsigned short*)&h;
    base[64 * CI + o * CI + k] = *(unsigned short*)&l;
}

// ---------------- merged prep + compaction fill kernel -----------------------
__global__ void prep_fill_kernel(const int* __restrict__ up_src,
                                 const int* __restrict__ up_kidx,
                                 const int* __restrict__ nbr_src,
                                 const float4* __restrict__ feats2,
                                 const float* __restrict__ wup,
                                 const float* __restrict__ w1,
                                 const float* __restrict__ w2,
                                 int n2, int nbU, int nbNbr)
{
    __shared__ int sc[27], sb[27];
    const int tid = threadIdx.x;
    const int b = blockIdx.x;
    if (b < nbU) {
        int i = b * 256 + tid;
        if (tid < 8) sc[tid] = 0;
        __syncthreads();
        int t = 0, p = 0, s = 0;
        bool v = (i < n2);
        if (v) { t = up_kidx[i]; s = up_src[i]; p = atomicAdd(&sc[t], 1); }
        __syncthreads();
        if (tid < 8 && sc[tid] > 0) sb[tid] = atomicAdd(&g_cntup[tid], sc[tid]);
        __syncthreads();
        if (v) {
            int q = sb[t] + p;
            g_entup[t * n2 + q] = s;
            g_posup[i] = t * n2 + q;
        }
    } else if (b < nbU + nbNbr) {
        int j = (b - nbU) * 256 + tid;
        if (tid < 27) sc[tid] = 0;
        __syncthreads();
        int t = 0, p = 0, s = 0;
        bool inr = (j < 27 * n2), hit = false;
        if (inr) {
            t = j / n2;
            s = nbr_src[j];
            hit = (s != n2);
            if (hit) p = atomicAdd(&sc[t], 1);
        }
        __syncthreads();
        if (tid < 27 && sc[tid] > 0) sb[tid] = atomicAdd(&g_cnt[tid], sc[tid]);
        __syncthreads();
        if (inr) {
            if (hit) {
                int q = sb[t] + p;
                g_ent[t * n2 + q] = s;
                g_pos[j] = t * n2 + q;
            } else g_pos[j] = -1;
        }
    } else {
        const int T1 = n2 * 16;
        const int T2 = 8  * 128 * 64;
        const int T3 = 27 * 128 * 64;
        const int T4 = 27 * 64  * 64;
        const int total = T1 + T2 + T3 + T4;
        const int nbP = gridDim.x - nbU - nbNbr;
        for (int idx = (b - nbU - nbNbr) * 256 + tid; idx < total;
             idx += nbP * 256) {
            if (idx < T1) {
                ((float4*)g_x)[(size_t)(idx >> 4) * 32 + 16 + (idx & 15)] = feats2[idx];
            } else if (idx < T1 + T2) {
                wsplit_one<128>(wup, g_Bup, idx - T1);
            } else if (idx < T1 + T2 + T3) {
                wsplit_one<128>(w1, g_B1, idx - T1 - T2);
            } else {
                wsplit_one<64>(w2, g_B2, idx - T1 - T2 - T3);
            }
        }
    }
}

// ---------------- parallel tile-list builder (1 block) -----------------------
__global__ void build_tiles_kernel()
{
    __shared__ int pfx[28], pfxu[9];
    const int tid = threadIdx.x;
    if (tid == 0) {
        int a = 0;
        for (int t = 0; t < 27; ++t) { pfx[t] = a; a += (g_cnt[t] + 127) >> 7; }
        pfx[27] = a;
        g_ntiles = a;
        int bsum = 0;
        for (int t = 0; t < 8; ++t) { pfxu[t] = bsum; bsum += (g_cntup[t] + 127) >> 7; }
        pfxu[8] = bsum;
        g_ntilesu = bsum;
    }
    __syncthreads();
    const int nt = pfx[27], ntu = pfxu[8];
    for (int idx = tid; idx < nt; idx += blockDim.x) {
        int lo = 0, hi = 27;
        while (hi - lo > 1) { int mid = (lo + hi) >> 1; if (pfx[mid] <= idx) lo = mid; else hi = mid; }
        int base = (idx - pfx[lo]) << 7;
        g_tileT[idx] = lo;
        g_tileB[idx] = base;
        g_tileN[idx] = min(128, g_cnt[lo] - base);
    }
    for (int idx = tid; idx < ntu; idx += blockDim.x) {
        int lo = 0, hi = 8;
        while (hi - lo > 1) { int mid = (lo + hi) >> 1; if (pfxu[mid] <= idx) lo = mid; else hi = mid; }
        int base = (idx - pfxu[lo]) << 7;
        g_tileTu[idx] = lo;
        g_tileBu[idx] = base;
        g_tileNu[idx] = min(128, g_cntup[lo] - base);
    }
    __syncthreads();
    if (tid < 27) g_cnt[tid] = 0;
    if (tid < 8)  g_cntup[tid] = 0;
}

// ---------------- mma.sync + ldmatrix helpers --------------------------------
__device__ __forceinline__ void mma16816(float& c0, float& c1, float& c2, float& c3,
                                         uint32_t a0, uint32_t a1, uint32_t a2, uint32_t a3,
                                         uint32_t b0, uint32_t b1)
{
    asm volatile("mma.sync.aligned.m16n8k16.row.col.f32.bf16.bf16.f32 "
                 "{%0,%1,%2,%3}, {%4,%5,%6,%7}, {%8,%9}, {%0,%1,%2,%3};"
                 : "+f"(c0), "+f"(c1), "+f"(c2), "+f"(c3)
                 : "r"(a0), "r"(a1), "r"(a2), "r"(a3), "r"(b0), "r"(b1));
}

__device__ __forceinline__ void ldmx4(uint32_t& r0, uint32_t& r1,
                                      uint32_t& r2, uint32_t& r3, uint32_t a)
{
    asm volatile("ldmatrix.sync.aligned.m8n8.x4.shared.b16 {%0,%1,%2,%3}, [%4];"
                 : "=r"(r0), "=r"(r1), "=r"(r2), "=r"(r3) : "r"(a));
}

__device__ __forceinline__ uint32_t smem_u32(const void* p) {
    uint32_t a;
    asm("{ .reg .u64 t; cvta.to.shared.u64 t, %1; cvt.u32.u64 %0, t; }"
        : "=r"(a) : "l"(p));
    return a;
}

__device__ __forceinline__ uint32_t bits2(__nv_bfloat162 v) {
    return *(uint32_t*)&v;
}

// ---------------- phase A: dense MMA, K-split staging (56 KB smem) -----------
// BNMODE: 0 = stage raw; 1 = BN+ReLU cols 0..63 (kh==0); 2 = BN+ReLU all cols.
// K processed in 64-wide halves; A/B hi+lo staged per half into [.][72] tiles.
template <int CI, int BNMODE>
__global__ __launch_bounds__(256)
void conv_mma_kernel(const float* __restrict__ xsrc,
                     const unsigned short* __restrict__ btile,
                     const int* __restrict__ ent,
                     const int* __restrict__ tileT,
                     const int* __restrict__ tileB,
                     const int* __restrict__ tileN,
                     const int* __restrict__ ntp,
                     float* __restrict__ msg, int n2)
{
    constexpr int AST    = 72;                   // padded K-half row stride
    constexpr int HALVES = CI / 64;
    extern __shared__ unsigned short smem[];
    unsigned short* Ah = smem;                   // [128][72]
    unsigned short* Al = Ah + 128 * AST;
    unsigned short* Bh = Al + 128 * AST;         // [64][72]
    unsigned short* Bl = Bh + 64 * AST;
    int* esm = (int*)(Bl + 64 * AST);            // [128]

    const int tid = threadIdx.x, wid = tid >> 5, lane = tid & 31;
    const int gp = lane >> 2, tg = lane & 3;
    const int ntiles = *ntp;

    // per-lane ldmatrix row addresses (bytes)
    const uint32_t sbase = smem_u32(smem);
    const int lo16 = lane & 15, koct = lane >> 4;
    const uint32_t aoff = (uint32_t)(((wid * 16 + lo16) * AST + koct * 8) * 2);
    const uint32_t AhA = sbase + aoff;
    const uint32_t AlA = sbase + (uint32_t)(128 * AST * 2) + aoff;
    const uint32_t boff = (uint32_t)((lo16 * AST + koct * 8) * 2);
    const uint32_t BhA = sbase + (uint32_t)(2 * 128 * AST * 2) + boff;
    const uint32_t BlA = BhA + (uint32_t)(64 * AST * 2);
    constexpr uint32_t BROW16 = (uint32_t)(16 * AST * 2);

    for (int idx = blockIdx.x; idx < ntiles; idx += gridDim.x) {
        const int t = tileT[idx], base = tileB[idx], nv = tileN[idx];
        __syncthreads();    // smem free from previous tile / MMA
        if (tid < 128) esm[tid] = ent[(size_t)t * n2 + base + min(tid, nv - 1)];

        float acc[8][4];
        #pragma unroll
        for (int nt = 0; nt < 8; ++nt)
            #pragma unroll
            for (int j = 0; j < 4; ++j) acc[nt][j] = 0.f;

        #pragma unroll
        for (int kh = 0; kh < HALVES; ++kh) {
            __syncthreads();   // esm ready (kh=0) / previous half's MMA done

            // stage B half: rows [o][kh*64 .. kh*64+64) of both planes
            {
                const uint4* srcB = (const uint4*)(btile + (size_t)t * (2 * 64 * CI));
                constexpr int RB = CI / 8;                 // uint4 per full row
                uint4* dBh = (uint4*)Bh;
                uint4* dBl = (uint4*)Bl;
                #pragma unroll
                for (int i = tid; i < 64 * 8; i += 256) {
                    int o = i >> 3, q = i & 7;
                    int sidx = o * RB + kh * 8 + q;
                    dBh[o * 9 + q] = srcB[sidx];
                    dBl[o * 9 + q] = srcB[8 * CI + sidx];  // lo plane: +64*CI ushorts
                }
            }

            // stage A half: gather + optional BN/ReLU + bf16 hi/lo split
            {
                const float4* x4 = (const float4*)xsrc;
                constexpr int C4 = CI / 4;                 // float4 per full row
                uint2* dAh = (uint2*)Ah;
                uint2* dAl = (uint2*)Al;
                #pragma unroll
                for (int i = tid; i < 128 * 16; i += 256) {
                    int m = i >> 4, q = i & 15;
                    float4 v = __ldg(&x4[(size_t)esm[m] * C4 + kh * 16 + q]);
                    if (BNMODE == 2 || (BNMODE == 1 && kh == 0)) {
                        float4 sc = *(const float4*)(g_bn + q * 4);
                        float4 sh = *(const float4*)(g_bn + 64 + q * 4);
                        v.x = fmaxf(fmaf(v.x, sc.x, sh.x), 0.f);
                        v.y = fmaxf(fmaf(v.y, sc.y, sh.y), 0.f);
                        v.z = fmaxf(fmaf(v.z, sc.z, sh.z), 0.f);
                        v.w = fmaxf(fmaf(v.w, sc.w, sh.w), 0.f);
                    }
                    __nv_bfloat162 h01 = __floats2bfloat162_rn(v.x, v.y);
                    __nv_bfloat162 h23 = __floats2bfloat162_rn(v.z, v.w);
                    float2 f01 = __bfloat1622float2(h01);
                    float2 f23 = __bfloat1622float2(h23);
                    __nv_bfloat162 l01 = __floats2bfloat162_rn(v.x - f01.x, v.y - f01.y);
                    __nv_bfloat162 l23 = __floats2bfloat162_rn(v.z - f23.x, v.w - f23.y);
                    dAh[m * 18 + q] = make_uint2(bits2(h01), bits2(h23));
                    dAl[m * 18 + q] = make_uint2(bits2(l01), bits2(l23));
                }
            }
            __syncthreads();

            // MMA over this K-half (4 k-steps)
            #pragma unroll
            for (int s = 0; s < 4; ++s) {
                const uint32_t kb = (uint32_t)(s * 32);
                uint32_t A0, A1, A2, A3, L0, L1, L2, L3;
                ldmx4(A0, A1, A2, A3, AhA + kb);
                ldmx4(L0, L1, L2, L3, AlA + kb);
                #pragma unroll
                for (int p = 0; p < 4; ++p) {
                    uint32_t b0, b1, b2, b3;
                    ldmx4(b0, b1, b2, b3, BhA + p * BROW16 + kb);
                    mma16816(acc[2*p][0], acc[2*p][1], acc[2*p][2], acc[2*p][3],
                             A0, A1, A2, A3, b0, b2);
                    mma16816(acc[2*p+1][0], acc[2*p+1][1], acc[2*p+1][2], acc[2*p+1][3],
                             A0, A1, A2, A3, b1, b3);
                }
                #pragma unroll
                for (int p = 0; p < 4; ++p) {
                    uint32_t b0, b1, b2, b3;
                    ldmx4(b0, b1, b2, b3, BlA + p * BROW16 + kb);
                    mma16816(acc[2*p][0], acc[2*p][1], acc[2*p][2], acc[2*p][3],
                             A0, A1, A2, A3, b0, b2);
                    mma16816(acc[2*p+1][0], acc[2*p+1][1], acc[2*p+1][2], acc[2*p+1][3],
                             A0, A1, A2, A3, b1, b3);
                }
                #pragma unroll
                for (int p = 0; p < 4; ++p) {
                    uint32_t b0, b1, b2, b3;
                    ldmx4(b0, b1, b2, b3, BhA + p * BROW16 + kb);
                    mma16816(acc[2*p][0], acc[2*p][1], acc[2*p][2], acc[2*p][3],
                             L0, L1, L2, L3, b0, b2);
                    mma16816(acc[2*p+1][0], acc[2*p+1][1], acc[2*p+1][2], acc[2*p+1][3],
                             L0, L1, L2, L3, b1, b3);
                }
            }
        }

        // epilogue: write compacted msg rows (registers only; no smem access)
        int m0 = wid * 16 + gp;
        int m1 = m0 + 8;
        float* d0 = msg + (size_t)(t * n2 + base + m0) * 64 + tg * 2;
        float* d1 = msg + (size_t)(t * n2 + base + m1) * 64 + tg * 2;
        bool v0 = (m0 < nv), v1 = (m1 < nv);
        #pragma unroll
        for (int nt = 0; nt < 8; ++nt) {
            if (v0) *(float2*)(d0 + nt * 8) = make_float2(acc[nt][0], acc[nt][1]);
            if (v1) *(float2*)(d1 + nt * 8) = make_float2(acc[nt][2], acc[nt][3]);
        }
    }
}

// ---------------- phase B: gather-sum + BN partials, 64 rows/block -----------
__global__ __launch_bounds__(256)
void conv_sum_kernel(const float4* __restrict__ msg4, const int* __restrict__ pos,
                     float* __restrict__ pre, int n2)
{
    __shared__ float red[256 * 8];
    const int tid = threadIdx.x;
    const int base = blockIdx.x * 64;
    const int ro = tid >> 4, c4 = tid & 15;
    float s[4] = {0, 0, 0, 0}, s2[4] = {0, 0, 0, 0};
    #pragma unroll
    for (int rr = ro; rr < 64; rr += 16) {
        int r = base + rr;
        if (r >= n2) break;
        float4 a = make_float4(0, 0, 0, 0);
        #pragma unroll 1
        for (int t = 0; t < 27; ++t) {
            int p = pos[t * n2 + r];
            if (p >= 0) {
                float4 m = msg4[(size_t)p * 16 + c4];
                a.x += m.x; a.y += m.y; a.z += m.z; a.w += m.w;
            }
        }
        ((float4*)pre)[(size_t)r * 16 + c4] = a;
        s[0] += a.x; s2[0] = fmaf(a.x, a.x, s2[0]);
        s[1] += a.y; s2[1] = fmaf(a.y, a.y, s2[1]);
        s[2] += a.z; s2[2] = fmaf(a.z, a.z, s2[2]);
        s[3] += a.w; s2[3] = fmaf(a.w, a.w, s2[3]);
    }
    #pragma unroll
    for (int j = 0; j < 4; ++j) { red[tid * 8 + j] = s[j]; red[tid * 8 + 4 + j] = s2[j]; }
    __syncthreads();
    if (tid < 64) {
        int cq = tid >> 2, jj = tid & 3;
        float ts = 0, t2 = 0;
        #pragma unroll
        for (int k = 0; k < 16; ++k) {
            ts += red[(k * 16 + cq) * 8 + jj];
            t2 += red[(k * 16 + cq) * 8 + 4 + jj];
        }
        g_part[(blockIdx.x * 64 + tid) * 2]     = ts;
        g_part[(blockIdx.x * 64 + tid) * 2 + 1] = t2;
    }
}

__global__ __launch_bounds__(256)
void up_sum_kernel(const float4* __restrict__ msg4, int n2)
{
    __shared__ float red[256 * 8];
    const int tid = threadIdx.x;
    const int base = blockIdx.x * 64;
    const int ro = tid >> 4, c4 = tid & 15;
    float s[4] = {0, 0, 0, 0}, s2[4] = {0, 0, 0, 0};
    #pragma unroll
    for (int rr = ro; rr < 64; rr += 16) {
        int r = base + rr;
        if (r >= n2) break;
        float4 a = msg4[(size_t)g_posup[r] * 16 + c4];
        ((float4*)g_x)[(size_t)r * 32 + c4] = a;
        s[0] += a.x; s2[0] = fmaf(a.x, a.x, s2[0]);
        s[1] += a.y; s2[1] = fmaf(a.y, a.y, s2[1]);
        s[2] += a.z; s2[2] = fmaf(a.z, a.z, s2[2]);
        s[3] += a.w; s2[3] = fmaf(a.w, a.w, s2[3]);
    }
    #pragma unroll
    for (int j = 0; j < 4; ++j) { red[tid * 8 + j] = s[j]; red[tid * 8 + 4 + j] = s2[j]; }
    __syncthreads();
    if (tid < 64) {
        int cq = tid >> 2, jj = tid & 3;
        float ts = 0, t2 = 0;
        #pragma unroll
        for (int k = 0; k < 16; ++k) {
            ts += red[(k * 16 + cq) * 8 + jj];
            t2 += red[(k * 16 + cq) * 8 + 4 + jj];
        }
        g_part[(blockIdx.x * 64 + tid) * 2]     = ts;
        g_part[(blockIdx.x * 64 + tid) * 2 + 1] = t2;
    }
}

// ---------------- BN finalize: partials -> scale/shift (256 threads) ---------
__global__ void bn_final_kernel(const float* __restrict__ gamma,
                                const float* __restrict__ beta,
                                int n, int nparts)
{
    __shared__ float red[512];
    const int tid = threadIdx.x;
    const int c = tid & 63, sl = tid >> 6;
    float s = 0.f, s2 = 0.f;
    for (int g = sl; g < nparts; g += 4) {
        s  += g_part[(g * 64 + c) * 2];
        s2 += g_part[(g * 64 + c) * 2 + 1];
    }
    red[tid] = s; red[256 + tid] = s2;
    __syncthreads();
    if (tid < 64) {
        float ts = red[tid] + red[64 + tid] + red[128 + tid] + red[192 + tid];
        float t2 = red[256 + tid] + red[320 + tid] + red[384 + tid] + red[448 + tid];
        float invn = 1.f / (float)n;
        float mean = ts * invn;
        float var  = t2 * invn - mean * mean;
        float inv  = rsqrtf(var + 1e-5f);
        float scale = gamma[tid] * inv;
        g_bn[tid]      = scale;
        g_bn[64 + tid] = beta[tid] - mean * scale;
    }
}

// ---------------- final output apply (reads g_bn) ----------------------------
__global__ void bn_apply_out_kernel(float* __restrict__ buf, int n)
{
    const int tid = threadIdx.x;
    const int c   = tid & 63;
    const float scale = g_bn[c];
    const float shift = g_bn[64 + c];
    const int rstep = gridDim.x * 4;
    for (int r = blockIdx.x * 4 + (tid >> 6); r < n; r += rstep) {
        float v = fmaf(buf[(size_t)r * 64 + c], scale, shift);
        buf[(size_t)r * 64 + c] = fmaxf(v, 0.f);
    }
}

// ---------------- launch ------------------------------------------------------
extern "C" void kernel_launch(void* const* d_in, const int* in_sizes, int n_in,
                              void* d_out, int out_size)
{
    const float* feats1   = (const float*)d_in[0];
    const float* feats2   = (const float*)d_in[1];
    const float* w_up     = (const float*)d_in[2];
    const float* gamma_up = (const float*)d_in[3];
    const float* beta_up  = (const float*)d_in[4];
    const float* w1       = (const float*)d_in[5];
    const float* gamma1   = (const float*)d_in[6];
    const float* beta1    = (const float*)d_in[7];
    const float* w2       = (const float*)d_in[8];
    const float* gamma2   = (const float*)d_in[9];
    const float* beta2    = (const float*)d_in[10];
    const int*   up_src   = (const int*)d_in[11];
    const int*   up_kidx  = (const int*)d_in[12];
    const int*   nbr_src  = (const int*)d_in[13];
    float*       out      = (float*)d_out;

    const int n2 = in_sizes[1] / 64;

    float *x, *pre, *msg;
    int *ent, *entup;
    int *tileT, *tileB, *tileN, *tileTu, *tileBu, *tileNu, *ntp, *ntpu;
    unsigned short *Bup, *B1, *B2;
    cudaGetSymbolAddress((void**)&x,     g_x);
    cudaGetSymbolAddress((void**)&pre,   g_pre);
    cudaGetSymbolAddress((void**)&msg,   g_msg);
    cudaGetSymbolAddress((void**)&ent,   g_ent);
    cudaGetSymbolAddress((void**)&entup, g_entup);
    cudaGetSymbolAddress((void**)&Bup,   g_Bup);
    cudaGetSymbolAddress((void**)&B1,    g_B1);
    cudaGetSymbolAddress((void**)&B2,    g_B2);
    cudaGetSymbolAddress((void**)&tileT,  g_tileT);
    cudaGetSymbolAddress((void**)&tileB,  g_tileB);
    cudaGetSymbolAddress((void**)&tileN,  g_tileN);
    cudaGetSymbolAddress((void**)&tileTu, g_tileTu);
    cudaGetSymbolAddress((void**)&tileBu, g_tileBu);
    cudaGetSymbolAddress((void**)&tileNu, g_tileNu);
    cudaGetSymbolAddress((void**)&ntp,    g_ntiles);
    cudaGetSymbolAddress((void**)&ntpu,   g_ntilesu);
    const int* pos;
    cudaGetSymbolAddress((void**)&pos,   g_pos);

    // smem: (2*128*72 + 2*64*72)*2 + 512 = 56320 B (both CI)
    const int SMEMC = (2 * 128 * 72 + 2 * 64 * 72) * 2 + 512;
    cudaFuncSetAttribute(conv_mma_kernel<128, 0>,
                         cudaFuncAttributeMaxDynamicSharedMemorySize, SMEMC);
    cudaFuncSetAttribute(conv_mma_kernel<128, 1>,
                         cudaFuncAttributeMaxDynamicSharedMemorySize, SMEMC);
    cudaFuncSetAttribute(conv_mma_kernel<64, 2>,
                         cudaFuncAttributeMaxDynamicSharedMemorySize, SMEMC);

    const int nbSum = (n2 + 63) / 64;             // 938 blocks (<=1024 partials)
    const int nbU   = (n2 + 255) / 256;           // 235
    const int nbNbr = (27 * n2 + 255) / 256;      // 6329
    const int NB_PREP = 1024;
    const int NB_CONV = 1332;                     // 3 CTAs/SM * 148 SMs * 3
    const int NB_UP   = 592;

    // 0: merged prep + fills
    prep_fill_kernel<<<nbU + nbNbr + NB_PREP, 256>>>(
        up_src, up_kidx, nbr_src, (const float4*)feats2, w_up, w1, w2,
        n2, nbU, nbNbr);
    // 1: tile lists (+ counter reset for next call)
    build_tiles_kernel<<<1, 1024>>>();

    // 2: upsample MMA -> msg
    conv_mma_kernel<128, 0><<<NB_UP, 256, SMEMC>>>(feats1, Bup, entup,
                                                   tileTu, tileBu, tileNu, ntpu,
                                                   msg, n2);
    // 3: gather into x (raw) + partials
    up_sum_kernel<<<nbSum, 256>>>((const float4*)msg, n2);
    // 4: finalize BN_up
    bn_final_kernel<<<1, 256>>>(gamma_up, beta_up, n2, nbSum);

    // 5: conv1 (BN_up fused into staging of cols 0..63)
    conv_mma_kernel<128, 1><<<NB_CONV, 256, SMEMC>>>(x, B1, ent,
                                                     tileT, tileB, tileN, ntp,
                                                     msg, n2);
    // 6: conv1 sum + partials
    conv_sum_kernel<<<nbSum, 256>>>((const float4*)msg, pos, pre, n2);
    // 7: finalize BN1
    bn_final_kernel<<<1, 256>>>(gamma1, beta1, n2, nbSum);

    // 8: conv2 (BN1 fused into staging, all cols)
    conv_mma_kernel<64, 2><<<NB_CONV, 256, SMEMC>>>(pre, B2, ent,
                                                    tileT, tileB, tileN, ntp,
                                                    msg, n2);
    // 9: conv2 sum + partials
    conv_sum_kernel<<<nbSum, 256>>>((const float4*)msg, pos, out, n2);
    // 10: finalize BN2 + 11: apply to output
    bn_final_kernel<<<1, 256>>>(gamma2, beta2, n2, nbSum);
    bn_apply_out_kernel<<<256, 256>>>(out, n2);
}

// round 16
// speedup vs baseline: 1.0921x; 1.0921x over previous
#include <cuda_runtime.h>
#include <cuda_bf16.h>
#include <cuda_fp16.h>
#include <cstdint>

#define N1MAX 15000
#define N2MAX 60000

// ---------------- device scratch (static, no allocs) -------------------------
__device__ float g_x   [N2MAX * 128];                 // concat(x1 raw, feats2)
__device__ float g_pre [N2MAX * 64];                  // conv1 pre-BN
__device__ __half g_msg[27u * N2MAX * 64];            // per-entry MMA outputs (fp16)
__device__ int   g_ent  [27 * N2MAX];                 // per-tap compacted src
__device__ int   g_entup[ 8 * N2MAX];
__device__ int   g_pos  [27 * N2MAX];                 // (tap,i) -> slot or -1
__device__ int   g_posup[N2MAX];
__device__ int   g_cnt  [27];                         // zeroed by build_tiles
__device__ int   g_cntup[8];
// weight images: [t][part(hi,lo)][o(64)][k(CI)] bf16, k contiguous
__device__ unsigned short g_Bup[8  * 2 * 64 * 128];
__device__ unsigned short g_B1 [27 * 2 * 64 * 128];
__device__ unsigned short g_B2 [27 * 2 * 64 * 64];
__device__ float g_part[1024 * 64 * 2];               // BN partials (64-row blocks)
__device__ float g_bn  [128];                          // scale[64], shift[64]
// exact tile lists (parallel-built)
__device__ int g_tileT [13000];
__device__ int g_tileB [13000];
__device__ int g_tileN [13000];
__device__ int g_tileTu[4096];
__device__ int g_tileBu[4096];
__device__ int g_tileNu[4096];
__device__ int g_ntiles;
__device__ int g_ntilesu;

// ---------------- weight split (template CI -> shift divisions) --------------
template <int CI>
__device__ __forceinline__ void wsplit_one(const float* __restrict__ w,
                                           unsigned short* __restrict__ dst,
                                           int j) {
    constexpr int PER = CI * 64;
    int t = j / PER;
    int r = j & (PER - 1);
    int k = r >> 6;
    int o = r & 63;
    float v = w[j];
    __nv_bfloat16 h = __float2bfloat16(v);
    __nv_bfloat16 l = __float2bfloat16(v - __bfloat162float(h));
    unsigned short* base = dst + (size_t)t * (2 * 64 * CI);
    base[o * CI + k]           = *(unsigned short*)&h;
    base[64 * CI + o * CI + k] = *(unsigned short*)&l;
}

// ---------------- merged prep + compaction fill kernel -----------------------
__global__ void prep_fill_kernel(const int* __restrict__ up_src,
                                 const int* __restrict__ up_kidx,
                                 const int* __restrict__ nbr_src,
                                 const float4* __restrict__ feats2,
                                 const float* __restrict__ wup,
                                 const float* __restrict__ w1,
                                 const float* __restrict__ w2,
                                 int n2, int nbU, int nbNbr)
{
    __shared__ int sc[27], sb[27];
    const int tid = threadIdx.x;
    const int b = blockIdx.x;
    if (b < nbU) {
        int i = b * 256 + tid;
        if (tid < 8) sc[tid] = 0;
        __syncthreads();
        int t = 0, p = 0, s = 0;
        bool v = (i < n2);
        if (v) { t = up_kidx[i]; s = up_src[i]; p = atomicAdd(&sc[t], 1); }
        __syncthreads();
        if (tid < 8 && sc[tid] > 0) sb[tid] = atomicAdd(&g_cntup[tid], sc[tid]);
        __syncthreads();
        if (v) {
            int q = sb[t] + p;
            g_entup[t * n2 + q] = s;
            g_posup[i] = t * n2 + q;
        }
    } else if (b < nbU + nbNbr) {
        int j = (b - nbU) * 256 + tid;
        if (tid < 27) sc[tid] = 0;
        __syncthreads();
        int t = 0, p = 0, s = 0;
        bool inr = (j < 27 * n2), hit = false;
        if (inr) {
            t = j / n2;
            s = nbr_src[j];
            hit = (s != n2);
            if (hit) p = atomicAdd(&sc[t], 1);
        }
        __syncthreads();
        if (tid < 27 && sc[tid] > 0) sb[tid] = atomicAdd(&g_cnt[tid], sc[tid]);
        __syncthreads();
        if (inr) {
            if (hit) {
                int q = sb[t] + p;
                g_ent[t * n2 + q] = s;
                g_pos[j] = t * n2 + q;
            } else g_pos[j] = -1;
        }
    } else {
        const int T1 = n2 * 16;
        const int T2 = 8  * 128 * 64;
        const int T3 = 27 * 128 * 64;
        const int T4 = 27 * 64  * 64;
        const int total = T1 + T2 + T3 + T4;
        const int nbP = gridDim.x - nbU - nbNbr;
        for (int idx = (b - nbU - nbNbr) * 256 + tid; idx < total;
             idx += nbP * 256) {
            if (idx < T1) {
                ((float4*)g_x)[(size_t)(idx >> 4) * 32 + 16 + (idx & 15)] = feats2[idx];
            } else if (idx < T1 + T2) {
                wsplit_one<128>(wup, g_Bup, idx - T1);
            } else if (idx < T1 + T2 + T3) {
                wsplit_one<128>(w1, g_B1, idx - T1 - T2);
            } else {
                wsplit_one<64>(w2, g_B2, idx - T1 - T2 - T3);
            }
        }
    }
}

// ---------------- parallel tile-list builder (1 block) -----------------------
__global__ void build_tiles_kernel()
{
    __shared__ int pfx[28], pfxu[9];
    const int tid = threadIdx.x;
    if (tid == 0) {
        int a = 0;
        for (int t = 0; t < 27; ++t) { pfx[t] = a; a += (g_cnt[t] + 127) >> 7; }
        pfx[27] = a;
        g_ntiles = a;
        int bsum = 0;
        for (int t = 0; t < 8; ++t) { pfxu[t] = bsum; bsum += (g_cntup[t] + 127) >> 7; }
        pfxu[8] = bsum;
        g_ntilesu = bsum;
    }
    __syncthreads();
    const int nt = pfx[27], ntu = pfxu[8];
    for (int idx = tid; idx < nt; idx += blockDim.x) {
        int lo = 0, hi = 27;
        while (hi - lo > 1) { int mid = (lo + hi) >> 1; if (pfx[mid] <= idx) lo = mid; else hi = mid; }
        int base = (idx - pfx[lo]) << 7;
        g_tileT[idx] = lo;
        g_tileB[idx] = base;
        g_tileN[idx] = min(128, g_cnt[lo] - base);
    }
    for (int idx = tid; idx < ntu; idx += blockDim.x) {
        int lo = 0, hi = 8;
        while (hi - lo > 1) { int mid = (lo + hi) >> 1; if (pfxu[mid] <= idx) lo = mid; else hi = mid; }
        int base = (idx - pfxu[lo]) << 7;
        g_tileTu[idx] = lo;
        g_tileBu[idx] = base;
        g_tileNu[idx] = min(128, g_cntup[lo] - base);
    }
    __syncthreads();
    if (tid < 27) g_cnt[tid] = 0;
    if (tid < 8)  g_cntup[tid] = 0;
}

// ---------------- mma.sync + ldmatrix helpers --------------------------------
__device__ __forceinline__ void mma16816(float& c0, float& c1, float& c2, float& c3,
                                         uint32_t a0, uint32_t a1, uint32_t a2, uint32_t a3,
                                         uint32_t b0, uint32_t b1)
{
    asm volatile("mma.sync.aligned.m16n8k16.row.col.f32.bf16.bf16.f32 "
                 "{%0,%1,%2,%3}, {%4,%5,%6,%7}, {%8,%9}, {%0,%1,%2,%3};"
                 : "+f"(c0), "+f"(c1), "+f"(c2), "+f"(c3)
                 : "r"(a0), "r"(a1), "r"(a2), "r"(a3), "r"(b0), "r"(b1));
}

__device__ __forceinline__ void ldmx4(uint32_t& r0, uint32_t& r1,
                                      uint32_t& r2, uint32_t& r3, uint32_t a)
{
    asm volatile("ldmatrix.sync.aligned.m8n8.x4.shared.b16 {%0,%1,%2,%3}, [%4];"
                 : "=r"(r0), "=r"(r1), "=r"(r2), "=r"(r3) : "r"(a));
}

__device__ __forceinline__ uint32_t smem_u32(const void* p) {
    uint32_t a;
    asm("{ .reg .u64 t; cvta.to.shared.u64 t, %1; cvt.u32.u64 %0, t; }"
        : "=r"(a) : "l"(p));
    return a;
}

__device__ __forceinline__ uint32_t bits2(__nv_bfloat162 v) {
    return *(uint32_t*)&v;
}

// ---------------- phase A: dense MMA, K-split staging (56 KB smem) -----------
// BNMODE: 0 = stage raw; 1 = BN+ReLU cols 0..63 (kh==0); 2 = BN+ReLU all cols.
// Epilogue writes fp16 msg rows.
template <int CI, int BNMODE>
__global__ __launch_bounds__(256)
void conv_mma_kernel(const float* __restrict__ xsrc,
                     const unsigned short* __restrict__ btile,
                     const int* __restrict__ ent,
                     const int* __restrict__ tileT,
                     const int* __restrict__ tileB,
                     const int* __restrict__ tileN,
                     const int* __restrict__ ntp,
                     __half* __restrict__ msg, int n2)
{
    constexpr int AST    = 72;                   // padded K-half row stride
    constexpr int HALVES = CI / 64;
    extern __shared__ unsigned short smem[];
    unsigned short* Ah = smem;                   // [128][72]
    unsigned short* Al = Ah + 128 * AST;
    unsigned short* Bh = Al + 128 * AST;         // [64][72]
    unsigned short* Bl = Bh + 64 * AST;
    int* esm = (int*)(Bl + 64 * AST);            // [128]

    const int tid = threadIdx.x, wid = tid >> 5, lane = tid & 31;
    const int gp = lane >> 2, tg = lane & 3;
    const int ntiles = *ntp;

    const uint32_t sbase = smem_u32(smem);
    const int lo16 = lane & 15, koct = lane >> 4;
    const uint32_t aoff = (uint32_t)(((wid * 16 + lo16) * AST + koct * 8) * 2);
    const uint32_t AhA = sbase + aoff;
    const uint32_t AlA = sbase + (uint32_t)(128 * AST * 2) + aoff;
    const uint32_t boff = (uint32_t)((lo16 * AST + koct * 8) * 2);
    const uint32_t BhA = sbase + (uint32_t)(2 * 128 * AST * 2) + boff;
    const uint32_t BlA = BhA + (uint32_t)(64 * AST * 2);
    constexpr uint32_t BROW16 = (uint32_t)(16 * AST * 2);

    for (int idx = blockIdx.x; idx < ntiles; idx += gridDim.x) {
        const int t = tileT[idx], base = tileB[idx], nv = tileN[idx];
        __syncthreads();
        if (tid < 128) esm[tid] = ent[(size_t)t * n2 + base + min(tid, nv - 1)];

        float acc[8][4];
        #pragma unroll
        for (int nt = 0; nt < 8; ++nt)
            #pragma unroll
            for (int j = 0; j < 4; ++j) acc[nt][j] = 0.f;

        #pragma unroll
        for (int kh = 0; kh < HALVES; ++kh) {
            __syncthreads();

            // stage B half
            {
                const uint4* srcB = (const uint4*)(btile + (size_t)t * (2 * 64 * CI));
                constexpr int RB = CI / 8;
                uint4* dBh = (uint4*)Bh;
                uint4* dBl = (uint4*)Bl;
                #pragma unroll
                for (int i = tid; i < 64 * 8; i += 256) {
                    int o = i >> 3, q = i & 7;
                    int sidx = o * RB + kh * 8 + q;
                    dBh[o * 9 + q] = srcB[sidx];
                    dBl[o * 9 + q] = srcB[8 * CI + sidx];
                }
            }
            // stage A half: gather + optional BN/ReLU + bf16 hi/lo split
            {
                const float4* x4 = (const float4*)xsrc;
                constexpr int C4 = CI / 4;
                uint2* dAh = (uint2*)Ah;
                uint2* dAl = (uint2*)Al;
                #pragma unroll
                for (int i = tid; i < 128 * 16; i += 256) {
                    int m = i >> 4, q = i & 15;
                    float4 v = __ldg(&x4[(size_t)esm[m] * C4 + kh * 16 + q]);
                    if (BNMODE == 2 || (BNMODE == 1 && kh == 0)) {
                        float4 sc = *(const float4*)(g_bn + q * 4);
                        float4 sh = *(const float4*)(g_bn + 64 + q * 4);
                        v.x = fmaxf(fmaf(v.x, sc.x, sh.x), 0.f);
                        v.y = fmaxf(fmaf(v.y, sc.y, sh.y), 0.f);
                        v.z = fmaxf(fmaf(v.z, sc.z, sh.z), 0.f);
                        v.w = fmaxf(fmaf(v.w, sc.w, sh.w), 0.f);
                    }
                    __nv_bfloat162 h01 = __floats2bfloat162_rn(v.x, v.y);
                    __nv_bfloat162 h23 = __floats2bfloat162_rn(v.z, v.w);
                    float2 f01 = __bfloat1622float2(h01);
                    float2 f23 = __bfloat1622float2(h23);
                    __nv_bfloat162 l01 = __floats2bfloat162_rn(v.x - f01.x, v.y - f01.y);
                    __nv_bfloat162 l23 = __floats2bfloat162_rn(v.z - f23.x, v.w - f23.y);
                    dAh[m * 18 + q] = make_uint2(bits2(h01), bits2(h23));
                    dAl[m * 18 + q] = make_uint2(bits2(l01), bits2(l23));
                }
            }
            __syncthreads();

            #pragma unroll
            for (int s = 0; s < 4; ++s) {
                const uint32_t kb = (uint32_t)(s * 32);
                uint32_t A0, A1, A2, A3, L0, L1, L2, L3;
                ldmx4(A0, A1, A2, A3, AhA + kb);
                ldmx4(L0, L1, L2, L3, AlA + kb);
                #pragma unroll
                for (int p = 0; p < 4; ++p) {
                    uint32_t b0, b1, b2, b3;
                    ldmx4(b0, b1, b2, b3, BhA + p * BROW16 + kb);
                    mma16816(acc[2*p][0], acc[2*p][1], acc[2*p][2], acc[2*p][3],
                             A0, A1, A2, A3, b0, b2);
                    mma16816(acc[2*p+1][0], acc[2*p+1][1], acc[2*p+1][2], acc[2*p+1][3],
                             A0, A1, A2, A3, b1, b3);
                }
                #pragma unroll
                for (int p = 0; p < 4; ++p) {
                    uint32_t b0, b1, b2, b3;
                    ldmx4(b0, b1, b2, b3, BlA + p * BROW16 + kb);
                    mma16816(acc[2*p][0], acc[2*p][1], acc[2*p][2], acc[2*p][3],
                             A0, A1, A2, A3, b0, b2);
                    mma16816(acc[2*p+1][0], acc[2*p+1][1], acc[2*p+1][2], acc[2*p+1][3],
                             A0, A1, A2, A3, b1, b3);
                }
                #pragma unroll
                for (int p = 0; p < 4; ++p) {
                    uint32_t b0, b1, b2, b3;
                    ldmx4(b0, b1, b2, b3, BhA + p * BROW16 + kb);
                    mma16816(acc[2*p][0], acc[2*p][1], acc[2*p][2], acc[2*p][3],
                             L0, L1, L2, L3, b0, b2);
                    mma16816(acc[2*p+1][0], acc[2*p+1][1], acc[2*p+1][2], acc[2*p+1][3],
                             L0, L1, L2, L3, b1, b3);
                }
            }
        }

        // epilogue: fp16 msg rows. row = 64 halves = 32 __half2; cols tg*2+nt*8
        int m0 = wid * 16 + gp;
        int m1 = m0 + 8;
        __half2* d0 = (__half2*)(msg + (size_t)(t * n2 + base + m0) * 64) + tg;
        __half2* d1 = (__half2*)(msg + (size_t)(t * n2 + base + m1) * 64) + tg;
        bool v0 = (m0 < nv), v1 = (m1 < nv);
        #pragma unroll
        for (int nt = 0; nt < 8; ++nt) {
            if (v0) d0[nt * 4] = __floats2half2_rn(acc[nt][0], acc[nt][1]);
            if (v1) d1[nt * 4] = __floats2half2_rn(acc[nt][2], acc[nt][3]);
        }
    }
}

// ---------------- phase B: gather-sum + BN partials, 64 rows/block -----------
__device__ __forceinline__ void acc_half4(float4& a, uint2 raw) {
    __half2 lo = *(__half2*)&raw.x, hi = *(__half2*)&raw.y;
    float2 f0 = __half22float2(lo), f1 = __half22float2(hi);
    a.x += f0.x; a.y += f0.y; a.z += f1.x; a.w += f1.y;
}

__global__ __launch_bounds__(256)
void conv_sum_kernel(const uint2* __restrict__ msg2, const int* __restrict__ pos,
                     float* __restrict__ pre, int n2)
{
    __shared__ float red[256 * 8];
    const int tid = threadIdx.x;
    const int base = blockIdx.x * 64;
    const int ro = tid >> 4, c4 = tid & 15;
    float s[4] = {0, 0, 0, 0}, s2[4] = {0, 0, 0, 0};
    #pragma unroll
    for (int rr = ro; rr < 64; rr += 16) {
        int r = base + rr;
        if (r >= n2) break;
        float4 a = make_float4(0, 0, 0, 0);
        for (int t = 0; t < 27; ++t) {           // unroll allowed: batch loads
            int p = pos[t * n2 + r];
            if (p >= 0) acc_half4(a, msg2[(size_t)p * 16 + c4]);
        }
        ((float4*)pre)[(size_t)r * 16 + c4] = a;
        s[0] += a.x; s2[0] = fmaf(a.x, a.x, s2[0]);
        s[1] += a.y; s2[1] = fmaf(a.y, a.y, s2[1]);
        s[2] += a.z; s2[2] = fmaf(a.z, a.z, s2[2]);
        s[3] += a.w; s2[3] = fmaf(a.w, a.w, s2[3]);
    }
    #pragma unroll
    for (int j = 0; j < 4; ++j) { red[tid * 8 + j] = s[j]; red[tid * 8 + 4 + j] = s2[j]; }
    __syncthreads();
    if (tid < 64) {
        int cq = tid >> 2, jj = tid & 3;
        float ts = 0, t2 = 0;
        #pragma unroll
        for (int k = 0; k < 16; ++k) {
            ts += red[(k * 16 + cq) * 8 + jj];
            t2 += red[(k * 16 + cq) * 8 + 4 + jj];
        }
        g_part[(blockIdx.x * 64 + tid) * 2]     = ts;
        g_part[(blockIdx.x * 64 + tid) * 2 + 1] = t2;
    }
}

__global__ __launch_bounds__(256)
void up_sum_kernel(const uint2* __restrict__ msg2, int n2)
{
    __shared__ float red[256 * 8];
    const int tid = threadIdx.x;
    const int base = blockIdx.x * 64;
    const int ro = tid >> 4, c4 = tid & 15;
    float s[4] = {0, 0, 0, 0}, s2[4] = {0, 0, 0, 0};
    #pragma unroll
    for (int rr = ro; rr < 64; rr += 16) {
        int r = base + rr;
        if (r >= n2) break;
        float4 a = make_float4(0, 0, 0, 0);
        acc_half4(a, msg2[(size_t)g_posup[r] * 16 + c4]);
        ((float4*)g_x)[(size_t)r * 32 + c4] = a;
        s[0] += a.x; s2[0] = fmaf(a.x, a.x, s2[0]);
        s[1] += a.y; s2[1] = fmaf(a.y, a.y, s2[1]);
        s[2] += a.z; s2[2] = fmaf(a.z, a.z, s2[2]);
        s[3] += a.w; s2[3] = fmaf(a.w, a.w, s2[3]);
    }
    #pragma unroll
    for (int j = 0; j < 4; ++j) { red[tid * 8 + j] = s[j]; red[tid * 8 + 4 + j] = s2[j]; }
    __syncthreads();
    if (tid < 64) {
        int cq = tid >> 2, jj = tid & 3;
        float ts = 0, t2 = 0;
        #pragma unroll
        for (int k = 0; k < 16; ++k) {
            ts += red[(k * 16 + cq) * 8 + jj];
            t2 += red[(k * 16 + cq) * 8 + 4 + jj];
        }
        g_part[(blockIdx.x * 64 + tid) * 2]     = ts;
        g_part[(blockIdx.x * 64 + tid) * 2 + 1] = t2;
    }
}

// ---------------- BN finalize: partials -> scale/shift (256 threads) ---------
__global__ void bn_final_kernel(const float* __restrict__ gamma,
                                const float* __restrict__ beta,
                                int n, int nparts)
{
    __shared__ float red[512];
    const int tid = threadIdx.x;
    const int c = tid & 63, sl = tid >> 6;
    float s = 0.f, s2 = 0.f;
    for (int g = sl; g < nparts; g += 4) {
        s  += g_part[(g * 64 + c) * 2];
        s2 += g_part[(g * 64 + c) * 2 + 1];
    }
    red[tid] = s; red[256 + tid] = s2;
    __syncthreads();
    if (tid < 64) {
        float ts = red[tid] + red[64 + tid] + red[128 + tid] + red[192 + tid];
        float t2 = red[256 + tid] + red[320 + tid] + red[384 + tid] + red[448 + tid];
        float invn = 1.f / (float)n;
        float mean = ts * invn;
        float var  = t2 * invn - mean * mean;
        float inv  = rsqrtf(var + 1e-5f);
        float scale = gamma[tid] * inv;
        g_bn[tid]      = scale;
        g_bn[64 + tid] = beta[tid] - mean * scale;
    }
}

// ---------------- final output apply (reads g_bn) ----------------------------
__global__ void bn_apply_out_kernel(float* __restrict__ buf, int n)
{
    const int tid = threadIdx.x;
    const int c   = tid & 63;
    const float scale = g_bn[c];
    const float shift = g_bn[64 + c];
    const int rstep = gridDim.x * 4;
    for (int r = blockIdx.x * 4 + (tid >> 6); r < n; r += rstep) {
        float v = fmaf(buf[(size_t)r * 64 + c], scale, shift);
        buf[(size_t)r * 64 + c] = fmaxf(v, 0.f);
    }
}

// ---------------- launch ------------------------------------------------------
extern "C" void kernel_launch(void* const* d_in, const int* in_sizes, int n_in,
                              void* d_out, int out_size)
{
    const float* feats1   = (const float*)d_in[0];
    const float* feats2   = (const float*)d_in[1];
    const float* w_up     = (const float*)d_in[2];
    const float* gamma_up = (const float*)d_in[3];
    const float* beta_up  = (const float*)d_in[4];
    const float* w1       = (const float*)d_in[5];
    const float* gamma1   = (const float*)d_in[6];
    const float* beta1    = (const float*)d_in[7];
    const float* w2       = (const float*)d_in[8];
    const float* gamma2   = (const float*)d_in[9];
    const float* beta2    = (const float*)d_in[10];
    const int*   up_src   = (const int*)d_in[11];
    const int*   up_kidx  = (const int*)d_in[12];
    const int*   nbr_src  = (const int*)d_in[13];
    float*       out      = (float*)d_out;

    const int n2 = in_sizes[1] / 64;

    float *x, *pre;
    __half* msg;
    int *ent, *entup;
    int *tileT, *tileB, *tileN, *tileTu, *tileBu, *tileNu, *ntp, *ntpu;
    unsigned short *Bup, *B1, *B2;
    cudaGetSymbolAddress((void**)&x,     g_x);
    cudaGetSymbolAddress((void**)&pre,   g_pre);
    cudaGetSymbolAddress((void**)&msg,   g_msg);
    cudaGetSymbolAddress((void**)&ent,   g_ent);
    cudaGetSymbolAddress((void**)&entup, g_entup);
    cudaGetSymbolAddress((void**)&Bup,   g_Bup);
    cudaGetSymbolAddress((void**)&B1,    g_B1);
    cudaGetSymbolAddress((void**)&B2,    g_B2);
    cudaGetSymbolAddress((void**)&tileT,  g_tileT);
    cudaGetSymbolAddress((void**)&tileB,  g_tileB);
    cudaGetSymbolAddress((void**)&tileN,  g_tileN);
    cudaGetSymbolAddress((void**)&tileTu, g_tileTu);
    cudaGetSymbolAddress((void**)&tileBu, g_tileBu);
    cudaGetSymbolAddress((void**)&tileNu, g_tileNu);
    cudaGetSymbolAddress((void**)&ntp,    g_ntiles);
    cudaGetSymbolAddress((void**)&ntpu,   g_ntilesu);
    const int* pos;
    cudaGetSymbolAddress((void**)&pos,   g_pos);

    const int SMEMC = (2 * 128 * 72 + 2 * 64 * 72) * 2 + 512;  // 56320 B
    cudaFuncSetAttribute(conv_mma_kernel<128, 0>,
                         cudaFuncAttributeMaxDynamicSharedMemorySize, SMEMC);
    cudaFuncSetAttribute(conv_mma_kernel<128, 1>,
                         cudaFuncAttributeMaxDynamicSharedMemorySize, SMEMC);
    cudaFuncSetAttribute(conv_mma_kernel<64, 2>,
                         cudaFuncAttributeMaxDynamicSharedMemorySize, SMEMC);

    const int nbSum = (n2 + 63) / 64;
    const int nbU   = (n2 + 255) / 256;
    const int nbNbr = (27 * n2 + 255) / 256;
    const int NB_PREP = 1024;
    const int NB_CONV = 1332;
    const int NB_UP   = 592;

    // 0: merged prep + fills
    prep_fill_kernel<<<nbU + nbNbr + NB_PREP, 256>>>(
        up_src, up_kidx, nbr_src, (const float4*)feats2, w_up, w1, w2,
        n2, nbU, nbNbr);
    // 1: tile lists (+ counter reset for next call)
    build_tiles_kernel<<<1, 1024>>>();

    // 2: upsample MMA -> msg (fp16)
    conv_mma_kernel<128, 0><<<NB_UP, 256, SMEMC>>>(feats1, Bup, entup,
                                                   tileTu, tileBu, tileNu, ntpu,
                                                   msg, n2);
    // 3: gather into x (raw) + partials
    up_sum_kernel<<<nbSum, 256>>>((const uint2*)msg, n2);
    // 4: finalize BN_up
    bn_final_kernel<<<1, 256>>>(gamma_up, beta_up, n2, nbSum);

    // 5: conv1 (BN_up fused into staging of cols 0..63)
    conv_mma_kernel<128, 1><<<NB_CONV, 256, SMEMC>>>(x, B1, ent,
                                                     tileT, tileB, tileN, ntp,
                                                     msg, n2);
    // 6: conv1 sum + partials
    conv_sum_kernel<<<nbSum, 256>>>((const uint2*)msg, pos, pre, n2);
    // 7: finalize BN1
    bn_final_kernel<<<1, 256>>>(gamma1, beta1, n2, nbSum);

    // 8: conv2 (BN1 fused into staging, all cols)
    conv_mma_kernel<64, 2><<<NB_CONV, 256, SMEMC>>>(pre, B2, ent,
                                                    tileT, tileB, tileN, ntp,
                                                    msg, n2);
    // 9: conv2 sum + partials
    conv_sum_kernel<<<nbSum, 256>>>((const uint2*)msg, pos, out, n2);
    // 10: finalize BN2 + 11: apply to output
    bn_final_kernel<<<1, 256>>>(gamma2, beta2, n2, nbSum);
    bn_apply_out_kernel<<<256, 256>>>(out, n2);
}